// round 16
// baseline (speedup 1.0000x reference)
#include <cuda_runtime.h>
#include <cuda_fp16.h>
#include <cstdint>

// Problem constants
constexpr int S_LEN = 4096;
constexpr int DM    = 1024;
constexpr int NH    = 16;
constexpr int HD    = 64;
constexpr int QKV_N = 3 * DM;  // 3072

// q section scaled by 0.125*log2(e): softmax computed in exp2 domain.
constexpr float Q_SCALE = 0.125f * 1.4426950408889634f;

// Scratch device globals — fp16
__device__ __half g_x   [(size_t)S_LEN * DM];
__device__ __half g_wqkv[(size_t)QKV_N * DM];
__device__ __half g_wout[(size_t)DM * DM];
__device__ __half g_qkv [(size_t)S_LEN * QKV_N];
__device__ __half g_att [(size_t)S_LEN * DM];

// ---------------------------------------------------------------------------
// Helpers
// ---------------------------------------------------------------------------
__device__ __forceinline__ void cp_async16(void* smem_dst, const void* gmem_src) {
    uint32_t s = (uint32_t)__cvta_generic_to_shared(smem_dst);
    asm volatile("cp.async.cg.shared.global [%0], [%1], 16;" :: "r"(s), "l"(gmem_src));
}
__device__ __forceinline__ void cp_async16s(uint32_t smem_dst, const void* gmem_src) {
    asm volatile("cp.async.cg.shared.global [%0], [%1], 16;" :: "r"(smem_dst), "l"(gmem_src));
}
__device__ __forceinline__ void cp_commit() {
    asm volatile("cp.async.commit_group;");
}
template<int N>
__device__ __forceinline__ void cp_wait() {
    asm volatile("cp.async.wait_group %0;" :: "n"(N));
}
__device__ __forceinline__ uint32_t smem_u32(const void* p) {
    return (uint32_t)__cvta_generic_to_shared(p);
}
__device__ __forceinline__ float ex2(float x) {
    float y;
    asm("ex2.approx.ftz.f32 %0, %1;" : "=f"(y) : "f"(x));
    return y;
}
__device__ __forceinline__ uint32_t h2ex2(uint32_t x) {
    uint32_t y;
    asm("ex2.approx.f16x2 %0, %1;" : "=r"(y) : "r"(x));
    return y;
}
__device__ __forceinline__ void ldmx4(uint32_t r[4], uint32_t a) {
    asm volatile("ldmatrix.sync.aligned.m8n8.x4.shared.b16 {%0,%1,%2,%3}, [%4];"
                 : "=r"(r[0]), "=r"(r[1]), "=r"(r[2]), "=r"(r[3]) : "r"(a));
}
__device__ __forceinline__ void ldmx4t(uint32_t r[4], uint32_t a) {
    asm volatile("ldmatrix.sync.aligned.m8n8.x4.trans.shared.b16 {%0,%1,%2,%3}, [%4];"
                 : "=r"(r[0]), "=r"(r[1]), "=r"(r[2]), "=r"(r[3]) : "r"(a));
}
__device__ __forceinline__ void mma_f16(float c[4], const uint32_t a[4],
                                        uint32_t b0, uint32_t b1) {
    asm volatile(
        "mma.sync.aligned.m16n8k16.row.col.f32.f16.f16.f32 "
        "{%0,%1,%2,%3}, {%4,%5,%6,%7}, {%8,%9}, {%0,%1,%2,%3};"
        : "+f"(c[0]), "+f"(c[1]), "+f"(c[2]), "+f"(c[3])
        : "r"(a[0]), "r"(a[1]), "r"(a[2]), "r"(a[3]), "r"(b0), "r"(b1));
}
__device__ __forceinline__ uint32_t f2h2(float x, float y) {
    __half2 h = __floats2half2_rn(x, y);
    return *(uint32_t*)&h;
}
// XOR-seg swizzle for 128-byte rows: seg in [0,8), 16B units.
__device__ __forceinline__ uint32_t sw128(uint32_t row, uint32_t seg) {
    return row * 128 + (((seg ^ (row & 7)) & 7) * 16);
}

// ---------------------------------------------------------------------------
// fp32 -> fp16 conversion pre-pass: all three tensors, ONE launch
// ---------------------------------------------------------------------------
__global__ void cvt_all_kernel(const float* __restrict__ a, __half* __restrict__ oa, int na4,
                               const float* __restrict__ b, __half* __restrict__ ob, int nb4,
                               const float* __restrict__ c, __half* __restrict__ oc, int nc4) {
    int j = blockIdx.x * blockDim.x + threadIdx.x;
    const float* in; __half* out;
    if (j < na4) { in = a; out = oa; }
    else {
        j -= na4;
        if (j < nb4) { in = b; out = ob; }
        else {
            j -= nb4;
            if (j >= nc4) return;
            in = c; out = oc;
        }
    }
    float4 v = ((const float4*)in)[j];
    ((__half2*)out)[j * 2 + 0] = __floats2half2_rn(v.x, v.y);
    ((__half2*)out)[j * 2 + 1] = __floats2half2_rn(v.z, v.w);
}

// ---------------------------------------------------------------------------
// FP16 GEMM: C[M,N]=A[M,K]*B[N,K]^T, fp32 accum.
// Block 128x128, 128 threads / 4 warps, 64x64 warp tiles (minimal L2 traffic).
// K-chunk 64, 3-stage cp.async pipeline, prefetch distance 2 (cp_wait<1>),
// one barrier per 64-K.  Smem 110592 B -> 2 blocks/SM.
// MODE 1: fp16 out; q cols (col<DM) scaled by Q_SCALE.  MODE 0: fp32 out.
// ---------------------------------------------------------------------------
constexpr int G_STRIDE  = 144;                 // bytes per smem row (64 halves + pad)
constexpr int G_STAGE   = 128 * G_STRIDE;      // 18432 B per operand stage
constexpr int GSTG      = 3;
constexpr int GEMM_SMEM = GSTG * 2 * G_STAGE;  // 110592 B

template<int MODE>
__global__ __launch_bounds__(128) void gemm_f16(
    const __half* __restrict__ A, const __half* __restrict__ B,
    void* __restrict__ Cv, int M, int N, int K)
{
    extern __shared__ char sm[];
    char* AsBase = sm;
    char* BsBase = sm + GSTG * G_STAGE;

    const int tid  = threadIdx.x;
    const int lane = tid & 31;
    const int wid  = tid >> 5;
    const int wm   = (wid >> 1) * 64;
    const int wn   = (wid & 1) * 64;
    const int m0   = blockIdx.y * 128;
    const int n0   = blockIdx.x * 128;
    const int NI   = K / 64;

    const int grp = lane >> 3, rw = lane & 7;
    const int a_row = (grp & 1) * 8 + rw;
    const int a_byt = (grp >> 1) * 16;
    const int b_row = (grp >> 1) * 8 + rw;
    const int b_byt = (grp & 1) * 16;

    auto issue_tile = [&](int it, int buf) {
        const char* Ag = (const char*)(A + (size_t)m0 * K + it * 64);
        const char* Bg = (const char*)(B + (size_t)n0 * K + it * 64);
        char* As = AsBase + buf * G_STAGE;
        char* Bs = BsBase + buf * G_STAGE;
#pragma unroll
        for (int p = 0; p < 8; ++p) {          // 128 rows x 8 segs = 1024
            int idx = tid + p * 128;
            int row = idx >> 3;
            int seg = (idx & 7) * 16;
            cp_async16(As + row * G_STRIDE + seg, Ag + (size_t)row * K * 2 + seg);
            cp_async16(Bs + row * G_STRIDE + seg, Bg + (size_t)row * K * 2 + seg);
        }
        cp_commit();
    };

    float acc[4][8][4];
#pragma unroll
    for (int i = 0; i < 4; ++i)
#pragma unroll
        for (int j = 0; j < 8; ++j)
#pragma unroll
            for (int c = 0; c < 4; ++c) acc[i][j][c] = 0.f;

    issue_tile(0, 0);
    issue_tile(1, 1);

    for (int it = 0; it < NI; ++it) {
        if (it + 1 < NI) cp_wait<1>(); else cp_wait<0>();
        __syncthreads();                        // one barrier per 64-K
        if (it + 2 < NI) issue_tile(it + 2, (it + 2) % GSTG);

        const uint32_t a_base = smem_u32(AsBase + (it % GSTG) * G_STAGE);
        const uint32_t b_base = smem_u32(BsBase + (it % GSTG) * G_STAGE);

#pragma unroll
        for (int ks = 0; ks < 4; ++ks) {
            uint32_t a[4][4], b[4][4];
#pragma unroll
            for (int mt = 0; mt < 4; ++mt)
                ldmx4(a[mt], a_base + (wm + mt * 16 + a_row) * G_STRIDE
                              + ks * 32 + a_byt);
#pragma unroll
            for (int u = 0; u < 4; ++u)
                ldmx4(b[u], b_base + (wn + u * 16 + b_row) * G_STRIDE
                             + ks * 32 + b_byt);
#pragma unroll
            for (int mt = 0; mt < 4; ++mt)
#pragma unroll
                for (int u = 0; u < 4; ++u) {
                    mma_f16(acc[mt][2 * u],     a[mt], b[u][0], b[u][1]);
                    mma_f16(acc[mt][2 * u + 1], a[mt], b[u][2], b[u][3]);
                }
        }
    }

    // Epilogue
#pragma unroll
    for (int mt = 0; mt < 4; ++mt) {
#pragma unroll
        for (int nt = 0; nt < 8; ++nt) {
            int row = m0 + wm + mt * 16 + (lane >> 2);
            int col = n0 + wn + nt * 8 + 2 * (lane & 3);
            if (MODE == 1) {
                __half* C = (__half*)Cv;
                float s = (col < DM) ? Q_SCALE : 1.0f;
                *(__half2*)&C[(size_t)row * N + col] =
                    __floats2half2_rn(acc[mt][nt][0] * s, acc[mt][nt][1] * s);
                *(__half2*)&C[(size_t)(row + 8) * N + col] =
                    __floats2half2_rn(acc[mt][nt][2] * s, acc[mt][nt][3] * s);
            } else {
                float* C = (float*)Cv;
                *(float2*)&C[(size_t)row * N + col] =
                    make_float2(acc[mt][nt][0], acc[mt][nt][1]);
                *(float2*)&C[(size_t)(row + 8) * N + col] =
                    make_float2(acc[mt][nt][2], acc[mt][nt][3]);
            }
        }
    }
}

// ---------------------------------------------------------------------------
// Flash attention (unchanged from R15): fp16 mma + ldmatrix, 128-col KV
// pairs, f16x2 exp2 path, XOR-swizzled 128 B rows, 3 blocks/SM.
// ---------------------------------------------------------------------------
constexpr int F_TILE   = 64 * 128;             // 8192 B
constexpr int F_PAIR   = 2 * F_TILE;           // 16384 B
constexpr int FL_SMEM  = F_TILE + 4 * F_PAIR;  // 73728 B

__global__ __launch_bounds__(128, 3) void flash_f16(
    const __half* __restrict__ qkv, __half* __restrict__ out)
{
    extern __shared__ char fsm[];
    const uint32_t q_base = smem_u32(fsm);
    const uint32_t k_base0 = q_base + F_TILE;
    const uint32_t v_base0 = q_base + F_TILE + 2 * F_PAIR;

    const int tid  = threadIdx.x;
    const int lane = tid & 31;
    const int w    = tid >> 5;
    const int h    = blockIdx.y;
    const int qt   = (int)gridDim.x - 1 - (int)blockIdx.x;  // heavy first
    const int q0   = qt * 64;
    const int pmax = qt >> 1;

    const int grp = lane >> 3, rw = lane & 7;
    const int q_row = (grp & 1) * 8 + rw;
    const int q_seg = grp >> 1;
    const int k_row = (grp >> 1) * 8 + rw;
    const int k_seg = grp & 1;
    const int v_row = (grp & 1) * 8 + rw;
    const int v_seg = grp >> 1;

    const char* qg = (const char*)(qkv + (size_t)q0 * QKV_N + h * HD);

    auto issue_pair = [&](int p, int buf) {
        uint32_t Ks = k_base0 + buf * F_PAIR;
        uint32_t Vs = v_base0 + buf * F_PAIR;
#pragma unroll
        for (int half = 0; half < 2; ++half) {
            int tile = 2 * p + half;
            if (tile > S_LEN / 64 - 1) tile = S_LEN / 64 - 1;
            const char* kg = (const char*)(qkv + (size_t)(tile * 64) * QKV_N + DM + h * HD);
            const char* vg = kg + DM * 2;
#pragma unroll
            for (int pp = 0; pp < 4; ++pp) {
                int idx = tid + pp * 128;
                int row = idx >> 3;
                int seg = idx & 7;
                uint32_t off = sw128(half * 64 + row, seg);
                cp_async16s(Ks + off, kg + (size_t)row * QKV_N * 2 + seg * 16);
                cp_async16s(Vs + off, vg + (size_t)row * QKV_N * 2 + seg * 16);
            }
        }
        cp_commit();
    };

    // Prologue: Q then pair 0
    {
#pragma unroll
        for (int pp = 0; pp < 4; ++pp) {
            int idx = tid + pp * 128;
            int row = idx >> 3;
            int seg = idx & 7;
            cp_async16s(q_base + sw128(row, seg),
                        qg + (size_t)row * QKV_N * 2 + seg * 16);
        }
        cp_commit();
    }
    issue_pair(0, 0);

    const int r  = (lane >> 2);
    const int qr = w * 16 + r;
    uint32_t Qf[4][4];
    float m_i[2] = {-1e30f, -1e30f};
    float l_i[2] = {0.f, 0.f};
    float oacc[8][4];
#pragma unroll
    for (int n = 0; n < 8; ++n)
#pragma unroll
        for (int c = 0; c < 4; ++c) oacc[n][c] = 0.f;

    for (int p = 0; p <= pmax; ++p) {
        cp_wait<0>();
        __syncthreads();
        if (p + 1 <= pmax) issue_pair(p + 1, (p + 1) & 1);

        if (p == 0) {
#pragma unroll
            for (int ks = 0; ks < 4; ++ks)
                ldmx4(Qf[ks], q_base + sw128(w * 16 + q_row, ks * 2 + q_seg));
        }

        const uint32_t k_base = k_base0 + (p & 1) * F_PAIR;
        const uint32_t v_base = v_base0 + (p & 1) * F_PAIR;

        // S = Q K^T over 128 cols
        float sacc[16][4];
#pragma unroll
        for (int n = 0; n < 16; ++n)
#pragma unroll
            for (int c = 0; c < 4; ++c) sacc[n][c] = 0.f;

#pragma unroll
        for (int ks = 0; ks < 4; ++ks) {
#pragma unroll
            for (int u = 0; u < 8; ++u) {
                uint32_t b[4];
                ldmx4(b, k_base + sw128(u * 16 + k_row, ks * 2 + k_seg));
                mma_f16(sacc[2 * u],     Qf[ks], b[0], b[1]);
                mma_f16(sacc[2 * u + 1], Qf[ks], b[2], b[3]);
            }
        }

        // Causal mask — only the last pair straddles/exceeds the diagonal
        if (p == pmax) {
#pragma unroll
            for (int nt = 0; nt < 16; ++nt) {
#pragma unroll
                for (int c = 0; c < 4; ++c) {
                    int col_g = p * 128 + nt * 8 + 2 * (lane & 3) + (c & 1);
                    int row_g = q0 + qr + (c >> 1) * 8;
                    if (col_g > row_g) sacc[nt][c] = -1e30f;
                }
            }
        }

        // Online softmax (exp2 domain), P via ex2.approx.f16x2.
        float alpha[2];
        uint32_t pa[8][4];
#pragma unroll
        for (int half = 0; half < 2; ++half) {
            float mx = -1e30f;
#pragma unroll
            for (int nt = 0; nt < 16; ++nt) {
                mx = fmaxf(mx, sacc[nt][half * 2]);
                mx = fmaxf(mx, sacc[nt][half * 2 + 1]);
            }
            mx = fmaxf(mx, __shfl_xor_sync(0xffffffffu, mx, 1, 4));
            mx = fmaxf(mx, __shfl_xor_sync(0xffffffffu, mx, 2, 4));
            float mnew = fmaxf(m_i[half], mx);
            alpha[half] = ex2(m_i[half] - mnew);
            m_i[half] = mnew;
            float rs = 0.f;
#pragma unroll
            for (int nt = 0; nt < 16; ++nt) {
                uint32_t hp = h2ex2(f2h2(sacc[nt][half * 2]     - mnew,
                                         sacc[nt][half * 2 + 1] - mnew));
                pa[nt >> 1][(nt & 1) * 2 + half] = hp;
                float2 f = __half22float2(*(__half2*)&hp);
                rs += f.x + f.y;
            }
            rs += __shfl_xor_sync(0xffffffffu, rs, 1, 4);
            rs += __shfl_xor_sync(0xffffffffu, rs, 2, 4);
            l_i[half] = l_i[half] * alpha[half] + rs;
        }

#pragma unroll
        for (int nt = 0; nt < 8; ++nt) {
            oacc[nt][0] *= alpha[0]; oacc[nt][1] *= alpha[0];
            oacc[nt][2] *= alpha[1]; oacc[nt][3] *= alpha[1];
        }

        // O += P V  (V via ldmatrix.trans)
#pragma unroll
        for (int ks = 0; ks < 8; ++ks) {
#pragma unroll
            for (int u = 0; u < 4; ++u) {
                uint32_t b[4];
                ldmx4t(b, v_base + sw128(ks * 16 + v_row, u * 2 + v_seg));
                mma_f16(oacc[2 * u],     pa[ks], b[0], b[1]);
                mma_f16(oacc[2 * u + 1], pa[ks], b[2], b[3]);
            }
        }
    }

    // Epilogue
    float inv0 = 1.f / l_i[0];
    float inv1 = 1.f / l_i[1];
#pragma unroll
    for (int nt = 0; nt < 8; ++nt) {
        int col = h * HD + nt * 8 + 2 * (lane & 3);
        int row = q0 + qr;
        *(__half2*)&out[(size_t)row * DM + col] =
            __floats2half2_rn(oacc[nt][0] * inv0, oacc[nt][1] * inv0);
        *(__half2*)&out[(size_t)(row + 8) * DM + col] =
            __floats2half2_rn(oacc[nt][2] * inv1, oacc[nt][3] * inv1);
    }
}

// ---------------------------------------------------------------------------
// Launch
// ---------------------------------------------------------------------------
extern "C" void kernel_launch(void* const* d_in, const int* in_sizes, int n_in,
                              void* d_out, int out_size)
{
    const float* x     = (const float*)d_in[0];
    const float* w_qkv = (const float*)d_in[1];
    const float* w_out = (const float*)d_in[2];
    float* out = (float*)d_out;

    __half *xr, *wqkvr, *woutr, *qkvp, *attp;
    cudaGetSymbolAddress((void**)&xr,    g_x);
    cudaGetSymbolAddress((void**)&wqkvr, g_wqkv);
    cudaGetSymbolAddress((void**)&woutr, g_wout);
    cudaGetSymbolAddress((void**)&qkvp,  g_qkv);
    cudaGetSymbolAddress((void**)&attp,  g_att);

    cudaFuncSetAttribute(gemm_f16<1>,
                         cudaFuncAttributeMaxDynamicSharedMemorySize, GEMM_SMEM);
    cudaFuncSetAttribute(gemm_f16<0>,
                         cudaFuncAttributeMaxDynamicSharedMemorySize, GEMM_SMEM);
    cudaFuncSetAttribute(flash_f16,
                         cudaFuncAttributeMaxDynamicSharedMemorySize, FL_SMEM);

    // 0) fp32 -> fp16 inputs, single launch
    {
        int na4 = S_LEN * DM / 4;
        int nb4 = QKV_N * DM / 4;
        int nc4 = DM * DM / 4;
        int ntot = na4 + nb4 + nc4;
        cvt_all_kernel<<<(ntot + 255) / 256, 256>>>(x, xr, na4, w_qkv, wqkvr, nb4,
                                                    w_out, woutr, nc4);
    }
    // 1) QKV projection (fp16 out; q scaled by 0.125*log2e)
    {
        dim3 grid(QKV_N / 128, S_LEN / 128);   // 24 x 32 = 768 blocks
        gemm_f16<1><<<grid, 128, GEMM_SMEM>>>(xr, wqkvr, qkvp, S_LEN, QKV_N, DM);
    }
    // 2) Flash attention (fp16 out)
    {
        dim3 grid(S_LEN / 64, NH);
        flash_f16<<<grid, 128, FL_SMEM>>>(qkvp, attp);
    }
    // 3) Output projection (fp32 out)
    {
        dim3 grid(DM / 128, S_LEN / 128);      // 8 x 32 = 256 blocks
        gemm_f16<0><<<grid, 128, GEMM_SMEM>>>(attp, woutr, out, S_LEN, DM, DM);
    }
}

// round 17
// speedup vs baseline: 1.0021x; 1.0021x over previous
#include <cuda_runtime.h>
#include <cuda_fp16.h>
#include <cstdint>

// Problem constants
constexpr int S_LEN = 4096;
constexpr int DM    = 1024;
constexpr int NH    = 16;
constexpr int HD    = 64;
constexpr int QKV_N = 3 * DM;  // 3072

// q section scaled by 0.125*log2(e): softmax computed in exp2 domain.
constexpr float Q_SCALE = 0.125f * 1.4426950408889634f;

// Scratch device globals — fp16
__device__ __half g_x   [(size_t)S_LEN * DM];
__device__ __half g_wqkv[(size_t)QKV_N * DM];
__device__ __half g_wout[(size_t)DM * DM];
__device__ __half g_qkv [(size_t)S_LEN * QKV_N];
__device__ __half g_att [(size_t)S_LEN * DM];

// ---------------------------------------------------------------------------
// Helpers
// ---------------------------------------------------------------------------
__device__ __forceinline__ void cp_async16(void* smem_dst, const void* gmem_src) {
    uint32_t s = (uint32_t)__cvta_generic_to_shared(smem_dst);
    asm volatile("cp.async.cg.shared.global [%0], [%1], 16;" :: "r"(s), "l"(gmem_src));
}
__device__ __forceinline__ void cp_async16s(uint32_t smem_dst, const void* gmem_src) {
    asm volatile("cp.async.cg.shared.global [%0], [%1], 16;" :: "r"(smem_dst), "l"(gmem_src));
}
__device__ __forceinline__ void cp_commit() {
    asm volatile("cp.async.commit_group;");
}
template<int N>
__device__ __forceinline__ void cp_wait() {
    asm volatile("cp.async.wait_group %0;" :: "n"(N));
}
__device__ __forceinline__ uint32_t smem_u32(const void* p) {
    return (uint32_t)__cvta_generic_to_shared(p);
}
__device__ __forceinline__ float ex2(float x) {
    float y;
    asm("ex2.approx.ftz.f32 %0, %1;" : "=f"(y) : "f"(x));
    return y;
}
__device__ __forceinline__ uint32_t h2ex2(uint32_t x) {
    uint32_t y;
    asm("ex2.approx.f16x2 %0, %1;" : "=r"(y) : "r"(x));
    return y;
}
__device__ __forceinline__ void ldmx4(uint32_t r[4], uint32_t a) {
    asm volatile("ldmatrix.sync.aligned.m8n8.x4.shared.b16 {%0,%1,%2,%3}, [%4];"
                 : "=r"(r[0]), "=r"(r[1]), "=r"(r[2]), "=r"(r[3]) : "r"(a));
}
__device__ __forceinline__ void ldmx4t(uint32_t r[4], uint32_t a) {
    asm volatile("ldmatrix.sync.aligned.m8n8.x4.trans.shared.b16 {%0,%1,%2,%3}, [%4];"
                 : "=r"(r[0]), "=r"(r[1]), "=r"(r[2]), "=r"(r[3]) : "r"(a));
}
__device__ __forceinline__ void mma_f16(float c[4], const uint32_t a[4],
                                        uint32_t b0, uint32_t b1) {
    asm volatile(
        "mma.sync.aligned.m16n8k16.row.col.f32.f16.f16.f32 "
        "{%0,%1,%2,%3}, {%4,%5,%6,%7}, {%8,%9}, {%0,%1,%2,%3};"
        : "+f"(c[0]), "+f"(c[1]), "+f"(c[2]), "+f"(c[3])
        : "r"(a[0]), "r"(a[1]), "r"(a[2]), "r"(a[3]), "r"(b0), "r"(b1));
}
__device__ __forceinline__ uint32_t f2h2(float x, float y) {
    __half2 h = __floats2half2_rn(x, y);
    return *(uint32_t*)&h;
}
// XOR-seg swizzle for 128-byte rows: seg in [0,8), 16B units.
__device__ __forceinline__ uint32_t sw128(uint32_t row, uint32_t seg) {
    return row * 128 + (((seg ^ (row & 7)) & 7) * 16);
}

// ---------------------------------------------------------------------------
// fp32 -> fp16 conversion pre-pass: all three tensors, ONE launch
// ---------------------------------------------------------------------------
__global__ void cvt_all_kernel(const float* __restrict__ a, __half* __restrict__ oa, int na4,
                               const float* __restrict__ b, __half* __restrict__ ob, int nb4,
                               const float* __restrict__ c, __half* __restrict__ oc, int nc4) {
    int j = blockIdx.x * blockDim.x + threadIdx.x;
    const float* in; __half* out;
    if (j < na4) { in = a; out = oa; }
    else {
        j -= na4;
        if (j < nb4) { in = b; out = ob; }
        else {
            j -= nb4;
            if (j >= nc4) return;
            in = c; out = oc;
        }
    }
    float4 v = ((const float4*)in)[j];
    ((__half2*)out)[j * 2 + 0] = __floats2half2_rn(v.x, v.y);
    ((__half2*)out)[j * 2 + 1] = __floats2half2_rn(v.z, v.w);
}

// ---------------------------------------------------------------------------
// FP16 GEMM (R12 config — best measured): C[M,N]=A[M,K]*B[N,K]^T, fp32 accum.
// Block 128x128, 128 threads / 4 warps, 64x64 warp tiles. K-chunk 64,
// 2-stage cp.async double buffer, one barrier per 64-K. 72 KB smem ->
// 3 blocks/SM (regs-capped).
// MODE 1: fp16 out; q cols (col<DM) scaled by Q_SCALE.  MODE 0: fp32 out.
// ---------------------------------------------------------------------------
constexpr int G_STRIDE  = 144;                 // bytes per smem row (64 halves + pad)
constexpr int G_STAGE   = 128 * G_STRIDE;      // 18432 B per operand stage
constexpr int GEMM_SMEM = 2 * 2 * G_STAGE;     // 73728 B

template<int MODE>
__global__ __launch_bounds__(128) void gemm_f16(
    const __half* __restrict__ A, const __half* __restrict__ B,
    void* __restrict__ Cv, int M, int N, int K)
{
    extern __shared__ char sm[];
    char* AsBase = sm;
    char* BsBase = sm + 2 * G_STAGE;

    const int tid  = threadIdx.x;
    const int lane = tid & 31;
    const int wid  = tid >> 5;
    const int wm   = (wid >> 1) * 64;
    const int wn   = (wid & 1) * 64;
    const int m0   = blockIdx.y * 128;
    const int n0   = blockIdx.x * 128;
    const int NI   = K / 64;

    const int grp = lane >> 3, rw = lane & 7;
    const int a_row = (grp & 1) * 8 + rw;
    const int a_byt = (grp >> 1) * 16;
    const int b_row = (grp >> 1) * 8 + rw;
    const int b_byt = (grp & 1) * 16;

    auto issue_tile = [&](int it, int buf) {
        const char* Ag = (const char*)(A + (size_t)m0 * K + it * 64);
        const char* Bg = (const char*)(B + (size_t)n0 * K + it * 64);
        char* As = AsBase + buf * G_STAGE;
        char* Bs = BsBase + buf * G_STAGE;
#pragma unroll
        for (int p = 0; p < 8; ++p) {           // 128 rows x 8 segs = 1024
            int idx = tid + p * 128;
            int row = idx >> 3;
            int seg = (idx & 7) * 16;
            cp_async16(As + row * G_STRIDE + seg, Ag + (size_t)row * K * 2 + seg);
            cp_async16(Bs + row * G_STRIDE + seg, Bg + (size_t)row * K * 2 + seg);
        }
        cp_commit();
    };

    float acc[4][8][4];
#pragma unroll
    for (int i = 0; i < 4; ++i)
#pragma unroll
        for (int j = 0; j < 8; ++j)
#pragma unroll
            for (int c = 0; c < 4; ++c) acc[i][j][c] = 0.f;

    issue_tile(0, 0);

    for (int it = 0; it < NI; ++it) {
        cp_wait<0>();
        __syncthreads();                        // one barrier per 64-K
        if (it + 1 < NI) issue_tile(it + 1, (it + 1) & 1);

        const uint32_t a_base = smem_u32(AsBase + (it & 1) * G_STAGE);
        const uint32_t b_base = smem_u32(BsBase + (it & 1) * G_STAGE);

#pragma unroll
        for (int ks = 0; ks < 4; ++ks) {
            uint32_t a[4][4], b[4][4];
#pragma unroll
            for (int mt = 0; mt < 4; ++mt)
                ldmx4(a[mt], a_base + (wm + mt * 16 + a_row) * G_STRIDE
                              + ks * 32 + a_byt);
#pragma unroll
            for (int u = 0; u < 4; ++u)
                ldmx4(b[u], b_base + (wn + u * 16 + b_row) * G_STRIDE
                             + ks * 32 + b_byt);
#pragma unroll
            for (int mt = 0; mt < 4; ++mt)
#pragma unroll
                for (int u = 0; u < 4; ++u) {
                    mma_f16(acc[mt][2 * u],     a[mt], b[u][0], b[u][1]);
                    mma_f16(acc[mt][2 * u + 1], a[mt], b[u][2], b[u][3]);
                }
        }
    }

    // Epilogue
#pragma unroll
    for (int mt = 0; mt < 4; ++mt) {
#pragma unroll
        for (int nt = 0; nt < 8; ++nt) {
            int row = m0 + wm + mt * 16 + (lane >> 2);
            int col = n0 + wn + nt * 8 + 2 * (lane & 3);
            if (MODE == 1) {
                __half* C = (__half*)Cv;
                float s = (col < DM) ? Q_SCALE : 1.0f;
                *(__half2*)&C[(size_t)row * N + col] =
                    __floats2half2_rn(acc[mt][nt][0] * s, acc[mt][nt][1] * s);
                *(__half2*)&C[(size_t)(row + 8) * N + col] =
                    __floats2half2_rn(acc[mt][nt][2] * s, acc[mt][nt][3] * s);
            } else {
                float* C = (float*)Cv;
                *(float2*)&C[(size_t)row * N + col] =
                    make_float2(acc[mt][nt][0], acc[mt][nt][1]);
                *(float2*)&C[(size_t)(row + 8) * N + col] =
                    make_float2(acc[mt][nt][2], acc[mt][nt][3]);
            }
        }
    }
}

// ---------------------------------------------------------------------------
// Flash attention (R15 base): fp16 mma + ldmatrix, 128-col KV pairs, f16x2
// exp2 path, XOR-swizzled 128 B rows, 3 blocks/SM.
// R17: for even qt, the upper 64 cols of the LAST pair are fully above the
// diagonal -> skip their S-mma and PV-mma entirely (bit-identical: those
// entries were masked to -1e30 -> P becomes exactly 0 in fp16).
// ---------------------------------------------------------------------------
constexpr int F_TILE   = 64 * 128;             // 8192 B
constexpr int F_PAIR   = 2 * F_TILE;           // 16384 B
constexpr int FL_SMEM  = F_TILE + 4 * F_PAIR;  // 73728 B

__global__ __launch_bounds__(128, 3) void flash_f16(
    const __half* __restrict__ qkv, __half* __restrict__ out)
{
    extern __shared__ char fsm[];
    const uint32_t q_base = smem_u32(fsm);
    const uint32_t k_base0 = q_base + F_TILE;
    const uint32_t v_base0 = q_base + F_TILE + 2 * F_PAIR;

    const int tid  = threadIdx.x;
    const int lane = tid & 31;
    const int w    = tid >> 5;
    const int h    = blockIdx.y;
    const int qt   = (int)gridDim.x - 1 - (int)blockIdx.x;  // heavy first
    const int q0   = qt * 64;
    const int pmax = qt >> 1;
    const bool qtEven = ((qt & 1) == 0);

    const int grp = lane >> 3, rw = lane & 7;
    const int q_row = (grp & 1) * 8 + rw;
    const int q_seg = grp >> 1;
    const int k_row = (grp >> 1) * 8 + rw;
    const int k_seg = grp & 1;
    const int v_row = (grp & 1) * 8 + rw;
    const int v_seg = grp >> 1;

    const char* qg = (const char*)(qkv + (size_t)q0 * QKV_N + h * HD);

    auto issue_pair = [&](int p, int buf) {
        uint32_t Ks = k_base0 + buf * F_PAIR;
        uint32_t Vs = v_base0 + buf * F_PAIR;
#pragma unroll
        for (int half = 0; half < 2; ++half) {
            int tile = 2 * p + half;   // always <= 63 (p <= 31)
            const char* kg = (const char*)(qkv + (size_t)(tile * 64) * QKV_N + DM + h * HD);
            const char* vg = kg + DM * 2;
#pragma unroll
            for (int pp = 0; pp < 4; ++pp) {
                int idx = tid + pp * 128;
                int row = idx >> 3;
                int seg = idx & 7;
                uint32_t off = sw128(half * 64 + row, seg);
                cp_async16s(Ks + off, kg + (size_t)row * QKV_N * 2 + seg * 16);
                cp_async16s(Vs + off, vg + (size_t)row * QKV_N * 2 + seg * 16);
            }
        }
        cp_commit();
    };

    // Prologue: Q then pair 0
    {
#pragma unroll
        for (int pp = 0; pp < 4; ++pp) {
            int idx = tid + pp * 128;
            int row = idx >> 3;
            int seg = idx & 7;
            cp_async16s(q_base + sw128(row, seg),
                        qg + (size_t)row * QKV_N * 2 + seg * 16);
        }
        cp_commit();
    }
    issue_pair(0, 0);

    const int r  = (lane >> 2);
    const int qr = w * 16 + r;
    uint32_t Qf[4][4];
    float m_i[2] = {-1e30f, -1e30f};
    float l_i[2] = {0.f, 0.f};
    float oacc[8][4];
#pragma unroll
    for (int n = 0; n < 8; ++n)
#pragma unroll
        for (int c = 0; c < 4; ++c) oacc[n][c] = 0.f;

    for (int p = 0; p <= pmax; ++p) {
        cp_wait<0>();
        __syncthreads();
        if (p + 1 <= pmax) issue_pair(p + 1, (p + 1) & 1);

        if (p == 0) {
#pragma unroll
            for (int ks = 0; ks < 4; ++ks)
                ldmx4(Qf[ks], q_base + sw128(w * 16 + q_row, ks * 2 + q_seg));
        }

        const uint32_t k_base = k_base0 + (p & 1) * F_PAIR;
        const uint32_t v_base = v_base0 + (p & 1) * F_PAIR;
        // Upper 64 cols of the last pair are fully masked when qt is even.
        const bool skipHi = (p == pmax) && qtEven;

        // S = Q K^T over 128 cols (lower 64 always; upper 64 unless skipHi)
        float sacc[16][4];
#pragma unroll
        for (int n = 0; n < 16; ++n)
#pragma unroll
            for (int c = 0; c < 4; ++c) sacc[n][c] = 0.f;

#pragma unroll
        for (int ks = 0; ks < 4; ++ks) {
#pragma unroll
            for (int u = 0; u < 4; ++u) {
                uint32_t b[4];
                ldmx4(b, k_base + sw128(u * 16 + k_row, ks * 2 + k_seg));
                mma_f16(sacc[2 * u],     Qf[ks], b[0], b[1]);
                mma_f16(sacc[2 * u + 1], Qf[ks], b[2], b[3]);
            }
        }
        if (!skipHi) {
#pragma unroll
            for (int ks = 0; ks < 4; ++ks) {
#pragma unroll
                for (int u = 4; u < 8; ++u) {
                    uint32_t b[4];
                    ldmx4(b, k_base + sw128(u * 16 + k_row, ks * 2 + k_seg));
                    mma_f16(sacc[2 * u],     Qf[ks], b[0], b[1]);
                    mma_f16(sacc[2 * u + 1], Qf[ks], b[2], b[3]);
                }
            }
        } else {
#pragma unroll
            for (int nt = 8; nt < 16; ++nt)
#pragma unroll
                for (int c = 0; c < 4; ++c) sacc[nt][c] = -1e30f;
        }

        // Causal mask — only the last pair straddles the diagonal
        if (p == pmax) {
#pragma unroll
            for (int nt = 0; nt < 16; ++nt) {
#pragma unroll
                for (int c = 0; c < 4; ++c) {
                    int col_g = p * 128 + nt * 8 + 2 * (lane & 3) + (c & 1);
                    int row_g = q0 + qr + (c >> 1) * 8;
                    if (col_g > row_g) sacc[nt][c] = -1e30f;
                }
            }
        }

        // Online softmax (exp2 domain), P via ex2.approx.f16x2.
        float alpha[2];
        uint32_t pa[8][4];
#pragma unroll
        for (int half = 0; half < 2; ++half) {
            float mx = -1e30f;
#pragma unroll
            for (int nt = 0; nt < 16; ++nt) {
                mx = fmaxf(mx, sacc[nt][half * 2]);
                mx = fmaxf(mx, sacc[nt][half * 2 + 1]);
            }
            mx = fmaxf(mx, __shfl_xor_sync(0xffffffffu, mx, 1, 4));
            mx = fmaxf(mx, __shfl_xor_sync(0xffffffffu, mx, 2, 4));
            float mnew = fmaxf(m_i[half], mx);
            alpha[half] = ex2(m_i[half] - mnew);
            m_i[half] = mnew;
            float rs = 0.f;
#pragma unroll
            for (int nt = 0; nt < 16; ++nt) {
                uint32_t hp = h2ex2(f2h2(sacc[nt][half * 2]     - mnew,
                                         sacc[nt][half * 2 + 1] - mnew));
                pa[nt >> 1][(nt & 1) * 2 + half] = hp;
                float2 f = __half22float2(*(__half2*)&hp);
                rs += f.x + f.y;
            }
            rs += __shfl_xor_sync(0xffffffffu, rs, 1, 4);
            rs += __shfl_xor_sync(0xffffffffu, rs, 2, 4);
            l_i[half] = l_i[half] * alpha[half] + rs;
        }

#pragma unroll
        for (int nt = 0; nt < 8; ++nt) {
            oacc[nt][0] *= alpha[0]; oacc[nt][1] *= alpha[0];
            oacc[nt][2] *= alpha[1]; oacc[nt][3] *= alpha[1];
        }

        // O += P V (rows 64..127 of the pair skipped when skipHi: P there = 0)
#pragma unroll
        for (int ks = 0; ks < 4; ++ks) {
#pragma unroll
            for (int u = 0; u < 4; ++u) {
                uint32_t b[4];
                ldmx4t(b, v_base + sw128(ks * 16 + v_row, u * 2 + v_seg));
                mma_f16(oacc[2 * u],     pa[ks], b[0], b[1]);
                mma_f16(oacc[2 * u + 1], pa[ks], b[2], b[3]);
            }
        }
        if (!skipHi) {
#pragma unroll
            for (int ks = 4; ks < 8; ++ks) {
#pragma unroll
                for (int u = 0; u < 4; ++u) {
                    uint32_t b[4];
                    ldmx4t(b, v_base + sw128(ks * 16 + v_row, u * 2 + v_seg));
                    mma_f16(oacc[2 * u],     pa[ks], b[0], b[1]);
                    mma_f16(oacc[2 * u + 1], pa[ks], b[2], b[3]);
                }
            }
        }
    }

    // Epilogue
    float inv0 = 1.f / l_i[0];
    float inv1 = 1.f / l_i[1];
#pragma unroll
    for (int nt = 0; nt < 8; ++nt) {
        int col = h * HD + nt * 8 + 2 * (lane & 3);
        int row = q0 + qr;
        *(__half2*)&out[(size_t)row * DM + col] =
            __floats2half2_rn(oacc[nt][0] * inv0, oacc[nt][1] * inv0);
        *(__half2*)&out[(size_t)(row + 8) * DM + col] =
            __floats2half2_rn(oacc[nt][2] * inv1, oacc[nt][3] * inv1);
    }
}

// ---------------------------------------------------------------------------
// Launch
// ---------------------------------------------------------------------------
extern "C" void kernel_launch(void* const* d_in, const int* in_sizes, int n_in,
                              void* d_out, int out_size)
{
    const float* x     = (const float*)d_in[0];
    const float* w_qkv = (const float*)d_in[1];
    const float* w_out = (const float*)d_in[2];
    float* out = (float*)d_out;

    __half *xr, *wqkvr, *woutr, *qkvp, *attp;
    cudaGetSymbolAddress((void**)&xr,    g_x);
    cudaGetSymbolAddress((void**)&wqkvr, g_wqkv);
    cudaGetSymbolAddress((void**)&woutr, g_wout);
    cudaGetSymbolAddress((void**)&qkvp,  g_qkv);
    cudaGetSymbolAddress((void**)&attp,  g_att);

    cudaFuncSetAttribute(gemm_f16<1>,
                         cudaFuncAttributeMaxDynamicSharedMemorySize, GEMM_SMEM);
    cudaFuncSetAttribute(gemm_f16<0>,
                         cudaFuncAttributeMaxDynamicSharedMemorySize, GEMM_SMEM);
    cudaFuncSetAttribute(flash_f16,
                         cudaFuncAttributeMaxDynamicSharedMemorySize, FL_SMEM);

    // 0) fp32 -> fp16 inputs, single launch
    {
        int na4 = S_LEN * DM / 4;
        int nb4 = QKV_N * DM / 4;
        int nc4 = DM * DM / 4;
        int ntot = na4 + nb4 + nc4;
        cvt_all_kernel<<<(ntot + 255) / 256, 256>>>(x, xr, na4, w_qkv, wqkvr, nb4,
                                                    w_out, woutr, nc4);
    }
    // 1) QKV projection (fp16 out; q scaled by 0.125*log2e)
    {
        dim3 grid(QKV_N / 128, S_LEN / 128);   // 24 x 32 = 768 blocks
        gemm_f16<1><<<grid, 128, GEMM_SMEM>>>(xr, wqkvr, qkvp, S_LEN, QKV_N, DM);
    }
    // 2) Flash attention (fp16 out)
    {
        dim3 grid(S_LEN / 64, NH);
        flash_f16<<<grid, 128, FL_SMEM>>>(qkvp, attp);
    }
    // 3) Output projection (fp32 out)
    {
        dim3 grid(DM / 128, S_LEN / 128);      // 8 x 32 = 256 blocks
        gemm_f16<0><<<grid, 128, GEMM_SMEM>>>(attp, woutr, out, S_LEN, DM, DM);
    }
}